// round 1
// baseline (speedup 1.0000x reference)
#include <cuda_runtime.h>

#define HID 128
#define TE 16
#define TN 16

// Scratch for scatter-add aggregation (segment_sum). N=50000, H=128.
__device__ float g_effects[50000 * 128];

__global__ void zero_effects_kernel(int n4) {
    int i = blockIdx.x * blockDim.x + threadIdx.x;
    float4* p = (float4*)g_effects;
    if (i < n4) p[i] = make_float4(0.f, 0.f, 0.f, 0.f);
}

// One layer of the MLP: acc[e] (thread = output column `tid`) over TILE rows
// staged in shared memory. Weights streamed from global (L2-hot).
template <int K, int TILE>
__device__ __forceinline__ void mlp_layer(const float* __restrict__ W, float bias,
                                          const float* sm_in, int in_stride,
                                          float* acc, int tid)
{
#pragma unroll
    for (int e = 0; e < TILE; e++) acc[e] = bias;
#pragma unroll 2
    for (int k = 0; k < K; k += 4) {
        float w0 = W[(k + 0) * HID + tid];
        float w1 = W[(k + 1) * HID + tid];
        float w2 = W[(k + 2) * HID + tid];
        float w3 = W[(k + 3) * HID + tid];
#pragma unroll
        for (int e = 0; e < TILE; e++) {
            float4 v = *(const float4*)(sm_in + e * in_stride + k);
            acc[e] = fmaf(v.x, w0, acc[e]);
            acc[e] = fmaf(v.y, w1, acc[e]);
            acc[e] = fmaf(v.z, w2, acc[e]);
            acc[e] = fmaf(v.w, w3, acc[e]);
        }
    }
}

// LayerNorm across the 128 columns held by the 128 threads, for TILE rows.
template <int TILE>
__device__ __forceinline__ void layernorm_tile(float* acc, float2* red, float2* mstd,
                                               float gam, float bet, int tid)
{
    const int warp = tid >> 5;
    const int lane = tid & 31;
#pragma unroll
    for (int e = 0; e < TILE; e++) {
        float s = acc[e];
        float q = s * s;
#pragma unroll
        for (int o = 16; o; o >>= 1) {
            s += __shfl_xor_sync(0xffffffffu, s, o);
            q += __shfl_xor_sync(0xffffffffu, q, o);
        }
        if (lane == 0) red[e * 4 + warp] = make_float2(s, q);
    }
    __syncthreads();
    if (tid < TILE) {
        float s = 0.f, q = 0.f;
#pragma unroll
        for (int w = 0; w < 4; w++) {
            float2 r = red[tid * 4 + w];
            s += r.x;
            q += r.y;
        }
        float m = s * (1.0f / 128.0f);
        float v = q * (1.0f / 128.0f) - m * m;
        mstd[tid] = make_float2(m, rsqrtf(v + 1e-5f));
    }
    __syncthreads();
#pragma unroll
    for (int e = 0; e < TILE; e++) {
        float2 ms = mstd[e];
        acc[e] = (acc[e] - ms.x) * ms.y * gam + bet;
    }
}

// -------------------- edge model --------------------
// h = relu(concat(dst, src, edge) @ ew1 + eb1); h = relu(h@ew2+eb2);
// edges_out = LN(h@ew3+eb3); effects[recv] += edges_out
__global__ __launch_bounds__(128) void edge_kernel(
    const float* __restrict__ nodes, const float* __restrict__ edges,
    const int* __restrict__ senders, const int* __restrict__ receivers,
    const float* __restrict__ ew1, const float* __restrict__ eb1,
    const float* __restrict__ ew2, const float* __restrict__ eb2,
    const float* __restrict__ ew3, const float* __restrict__ eb3,
    const float* __restrict__ egam, const float* __restrict__ ebet,
    float* __restrict__ edges_out, int E)
{
    __shared__ __align__(16) float h0[TE * 384];
    __shared__ __align__(16) float h1[TE * 128];
    __shared__ float2 red[TE * 4];
    __shared__ float2 mstd[TE];
    __shared__ int s_idx[2 * TE];  // [0..TE): receivers, [TE..2TE): senders

    const int tid = threadIdx.x;
    const int e0 = blockIdx.x * TE;

    if (tid < TE) {
        int e = e0 + tid;
        if (e >= E) e = E - 1;
        s_idx[tid] = receivers[e];
        s_idx[TE + tid] = senders[e];
    }
    __syncthreads();

    // Gather: concat(nodes[recv], nodes[send], edges[e]) -> h0[e][0:384]
    {
        const float4* n4 = (const float4*)nodes;
        const float4* ed4 = (const float4*)edges;
        float4* h0_4 = (float4*)h0;
        const int c4 = tid & 31;   // float4 column 0..31
        const int er = tid >> 5;   // edge-in-group 0..3
#pragma unroll
        for (int eg = 0; eg < TE; eg += 4) {
            int e = eg + er;
            int ge = e0 + e;
            if (ge >= E) ge = E - 1;
            int r = s_idx[e];
            int s = s_idx[TE + e];
            h0_4[e * 96 + c4]      = n4[(size_t)r * 32 + c4];
            h0_4[e * 96 + 32 + c4] = n4[(size_t)s * 32 + c4];
            h0_4[e * 96 + 64 + c4] = ed4[(size_t)ge * 32 + c4];
        }
    }
    __syncthreads();

    float acc[TE];

    // layer 1: 384 -> 128, relu
    mlp_layer<384, TE>(ew1, eb1[tid], h0, 384, acc, tid);
#pragma unroll
    for (int e = 0; e < TE; e++) h1[e * 128 + tid] = fmaxf(acc[e], 0.f);
    __syncthreads();  // all h0 reads done; h1 visible

    // layer 2: 128 -> 128, relu; write into h0 region (free now)
    mlp_layer<128, TE>(ew2, eb2[tid], h1, 128, acc, tid);
#pragma unroll
    for (int e = 0; e < TE; e++) h0[e * 128 + tid] = fmaxf(acc[e], 0.f);
    __syncthreads();

    // layer 3: 128 -> 128, then LayerNorm
    mlp_layer<128, TE>(ew3, eb3[tid], h0, 128, acc, tid);
    layernorm_tile<TE>(acc, red, mstd, egam[tid], ebet[tid], tid);

    // write edges_out + scatter-add into effects
#pragma unroll
    for (int e = 0; e < TE; e++) {
        int ge = e0 + e;
        if (ge < E) {
            edges_out[(size_t)ge * 128 + tid] = acc[e];
            atomicAdd(&g_effects[(size_t)s_idx[e] * 128 + tid], acc[e]);
        }
    }
}

// -------------------- node model --------------------
// x = relu(concat(nodes, effects)@nw1+nb1); x = relu(x@nw2+nb2);
// nodes_out = LN(x@nw3+nb3)
__global__ __launch_bounds__(128) void node_kernel(
    const float* __restrict__ nodes,
    const float* __restrict__ nw1, const float* __restrict__ nb1,
    const float* __restrict__ nw2, const float* __restrict__ nb2,
    const float* __restrict__ nw3, const float* __restrict__ nb3,
    const float* __restrict__ ngam, const float* __restrict__ nbet,
    float* __restrict__ nodes_out, int N)
{
    __shared__ __align__(16) float h0[TN * 256];
    __shared__ __align__(16) float h1[TN * 128];
    __shared__ float2 red[TN * 4];
    __shared__ float2 mstd[TN];

    const int tid = threadIdx.x;
    const int n0 = blockIdx.x * TN;

    // Gather: concat(nodes[n], effects[n]) -> h0[n][0:256]
    {
        const float4* n4 = (const float4*)nodes;
        const float4* f4 = (const float4*)g_effects;
        float4* h0_4 = (float4*)h0;
        const int c4 = tid & 31;
        const int nr = tid >> 5;
#pragma unroll
        for (int ng2 = 0; ng2 < TN; ng2 += 4) {
            int n = ng2 + nr;
            int gn = n0 + n;
            float4 a = make_float4(0.f, 0.f, 0.f, 0.f);
            float4 b = a;
            if (gn < N) {
                a = n4[(size_t)gn * 32 + c4];
                b = f4[(size_t)gn * 32 + c4];
            }
            h0_4[n * 64 + c4]      = a;
            h0_4[n * 64 + 32 + c4] = b;
        }
    }
    __syncthreads();

    float acc[TN];

    mlp_layer<256, TN>(nw1, nb1[tid], h0, 256, acc, tid);
#pragma unroll
    for (int n = 0; n < TN; n++) h1[n * 128 + tid] = fmaxf(acc[n], 0.f);
    __syncthreads();

    mlp_layer<128, TN>(nw2, nb2[tid], h1, 128, acc, tid);
#pragma unroll
    for (int n = 0; n < TN; n++) h0[n * 128 + tid] = fmaxf(acc[n], 0.f);
    __syncthreads();

    mlp_layer<128, TN>(nw3, nb3[tid], h0, 128, acc, tid);
    layernorm_tile<TN>(acc, red, mstd, ngam[tid], nbet[tid], tid);

#pragma unroll
    for (int n = 0; n < TN; n++) {
        int gn = n0 + n;
        if (gn < N) nodes_out[(size_t)gn * 128 + tid] = acc[n];
    }
}

extern "C" void kernel_launch(void* const* d_in, const int* in_sizes, int n_in,
                              void* d_out, int out_size)
{
    const float* nodes     = (const float*)d_in[0];
    const float* edges     = (const float*)d_in[1];
    const int*   senders   = (const int*)d_in[2];
    const int*   receivers = (const int*)d_in[3];
    const float* ew1 = (const float*)d_in[4];
    const float* eb1 = (const float*)d_in[5];
    const float* ew2 = (const float*)d_in[6];
    const float* eb2 = (const float*)d_in[7];
    const float* ew3 = (const float*)d_in[8];
    const float* eb3 = (const float*)d_in[9];
    const float* egam = (const float*)d_in[10];
    const float* ebet = (const float*)d_in[11];
    const float* nw1 = (const float*)d_in[12];
    const float* nb1 = (const float*)d_in[13];
    const float* nw2 = (const float*)d_in[14];
    const float* nb2 = (const float*)d_in[15];
    const float* nw3 = (const float*)d_in[16];
    const float* nb3 = (const float*)d_in[17];
    const float* ngam = (const float*)d_in[18];
    const float* nbet = (const float*)d_in[19];

    const int N = in_sizes[0] / HID;  // 50000
    const int E = in_sizes[2];        // 800000

    float* nodes_out = (float*)d_out;
    float* edges_out = nodes_out + (size_t)N * HID;

    // 1) zero the scatter-add accumulator
    const int n4 = N * (HID / 4);
    zero_effects_kernel<<<(n4 + 255) / 256, 256>>>(n4);

    // 2) edge MLP + LN + scatter-add
    edge_kernel<<<(E + TE - 1) / TE, 128>>>(
        nodes, edges, senders, receivers,
        ew1, eb1, ew2, eb2, ew3, eb3, egam, ebet,
        edges_out, E);

    // 3) node MLP + LN
    node_kernel<<<(N + TN - 1) / TN, 128>>>(
        nodes, nw1, nb1, nw2, nb2, nw3, nb3, ngam, nbet,
        nodes_out, N);
}

// round 2
// speedup vs baseline: 1.0013x; 1.0013x over previous
#include <cuda_runtime.h>

#define HID 128
#define TE 16
#define TN 16

// Scratch for scatter-add aggregation (segment_sum). N=50000, H=128.
__device__ float g_effects[50000 * 128];

__global__ void zero_effects_kernel(int n4) {
    int i = blockIdx.x * blockDim.x + threadIdx.x;
    float4* p = (float4*)g_effects;
    if (i < n4) p[i] = make_float4(0.f, 0.f, 0.f, 0.f);
}

// One layer of the MLP: acc[e] (thread = output column `tid`) over TILE rows
// staged in shared memory. Weights streamed from global (L2-hot).
template <int K, int TILE>
__device__ __forceinline__ void mlp_layer(const float* __restrict__ W, float bias,
                                          const float* sm_in, int in_stride,
                                          float* acc, int tid)
{
#pragma unroll
    for (int e = 0; e < TILE; e++) acc[e] = bias;
#pragma unroll 2
    for (int k = 0; k < K; k += 4) {
        float w0 = W[(k + 0) * HID + tid];
        float w1 = W[(k + 1) * HID + tid];
        float w2 = W[(k + 2) * HID + tid];
        float w3 = W[(k + 3) * HID + tid];
#pragma unroll
        for (int e = 0; e < TILE; e++) {
            float4 v = *(const float4*)(sm_in + e * in_stride + k);
            acc[e] = fmaf(v.x, w0, acc[e]);
            acc[e] = fmaf(v.y, w1, acc[e]);
            acc[e] = fmaf(v.z, w2, acc[e]);
            acc[e] = fmaf(v.w, w3, acc[e]);
        }
    }
}

// LayerNorm across the 128 columns held by the 128 threads, for TILE rows.
template <int TILE>
__device__ __forceinline__ void layernorm_tile(float* acc, float2* red, float2* mstd,
                                               float gam, float bet, int tid)
{
    const int warp = tid >> 5;
    const int lane = tid & 31;
#pragma unroll
    for (int e = 0; e < TILE; e++) {
        float s = acc[e];
        float q = s * s;
#pragma unroll
        for (int o = 16; o; o >>= 1) {
            s += __shfl_xor_sync(0xffffffffu, s, o);
            q += __shfl_xor_sync(0xffffffffu, q, o);
        }
        if (lane == 0) red[e * 4 + warp] = make_float2(s, q);
    }
    __syncthreads();
    if (tid < TILE) {
        float s = 0.f, q = 0.f;
#pragma unroll
        for (int w = 0; w < 4; w++) {
            float2 r = red[tid * 4 + w];
            s += r.x;
            q += r.y;
        }
        float m = s * (1.0f / 128.0f);
        float v = q * (1.0f / 128.0f) - m * m;
        mstd[tid] = make_float2(m, rsqrtf(v + 1e-5f));
    }
    __syncthreads();
#pragma unroll
    for (int e = 0; e < TILE; e++) {
        float2 ms = mstd[e];
        acc[e] = (acc[e] - ms.x) * ms.y * gam + bet;
    }
}

// -------------------- edge model --------------------
// h = relu(concat(dst, src, edge) @ ew1 + eb1); h = relu(h@ew2+eb2);
// edges_out = LN(h@ew3+eb3); effects[recv] += edges_out
__global__ __launch_bounds__(128) void edge_kernel(
    const float* __restrict__ nodes, const float* __restrict__ edges,
    const int* __restrict__ senders, const int* __restrict__ receivers,
    const float* __restrict__ ew1, const float* __restrict__ eb1,
    const float* __restrict__ ew2, const float* __restrict__ eb2,
    const float* __restrict__ ew3, const float* __restrict__ eb3,
    const float* __restrict__ egam, const float* __restrict__ ebet,
    float* __restrict__ edges_out, int E)
{
    __shared__ __align__(16) float h0[TE * 384];
    __shared__ __align__(16) float h1[TE * 128];
    __shared__ float2 red[TE * 4];
    __shared__ float2 mstd[TE];
    __shared__ int s_idx[2 * TE];  // [0..TE): receivers, [TE..2TE): senders

    const int tid = threadIdx.x;
    const int e0 = blockIdx.x * TE;

    if (tid < TE) {
        int e = e0 + tid;
        if (e >= E) e = E - 1;
        s_idx[tid] = receivers[e];
        s_idx[TE + tid] = senders[e];
    }
    __syncthreads();

    // Gather: concat(nodes[recv], nodes[send], edges[e]) -> h0[e][0:384]
    {
        const float4* n4 = (const float4*)nodes;
        const float4* ed4 = (const float4*)edges;
        float4* h0_4 = (float4*)h0;
        const int c4 = tid & 31;   // float4 column 0..31
        const int er = tid >> 5;   // edge-in-group 0..3
#pragma unroll
        for (int eg = 0; eg < TE; eg += 4) {
            int e = eg + er;
            int ge = e0 + e;
            if (ge >= E) ge = E - 1;
            int r = s_idx[e];
            int s = s_idx[TE + e];
            h0_4[e * 96 + c4]      = n4[(size_t)r * 32 + c4];
            h0_4[e * 96 + 32 + c4] = n4[(size_t)s * 32 + c4];
            h0_4[e * 96 + 64 + c4] = ed4[(size_t)ge * 32 + c4];
        }
    }
    __syncthreads();

    float acc[TE];

    // layer 1: 384 -> 128, relu
    mlp_layer<384, TE>(ew1, eb1[tid], h0, 384, acc, tid);
#pragma unroll
    for (int e = 0; e < TE; e++) h1[e * 128 + tid] = fmaxf(acc[e], 0.f);
    __syncthreads();  // all h0 reads done; h1 visible

    // layer 2: 128 -> 128, relu; write into h0 region (free now)
    mlp_layer<128, TE>(ew2, eb2[tid], h1, 128, acc, tid);
#pragma unroll
    for (int e = 0; e < TE; e++) h0[e * 128 + tid] = fmaxf(acc[e], 0.f);
    __syncthreads();

    // layer 3: 128 -> 128, then LayerNorm
    mlp_layer<128, TE>(ew3, eb3[tid], h0, 128, acc, tid);
    layernorm_tile<TE>(acc, red, mstd, egam[tid], ebet[tid], tid);

    // write edges_out + scatter-add into effects
#pragma unroll
    for (int e = 0; e < TE; e++) {
        int ge = e0 + e;
        if (ge < E) {
            edges_out[(size_t)ge * 128 + tid] = acc[e];
            atomicAdd(&g_effects[(size_t)s_idx[e] * 128 + tid], acc[e]);
        }
    }
}

// -------------------- node model --------------------
// x = relu(concat(nodes, effects)@nw1+nb1); x = relu(x@nw2+nb2);
// nodes_out = LN(x@nw3+nb3)
__global__ __launch_bounds__(128) void node_kernel(
    const float* __restrict__ nodes,
    const float* __restrict__ nw1, const float* __restrict__ nb1,
    const float* __restrict__ nw2, const float* __restrict__ nb2,
    const float* __restrict__ nw3, const float* __restrict__ nb3,
    const float* __restrict__ ngam, const float* __restrict__ nbet,
    float* __restrict__ nodes_out, int N)
{
    __shared__ __align__(16) float h0[TN * 256];
    __shared__ __align__(16) float h1[TN * 128];
    __shared__ float2 red[TN * 4];
    __shared__ float2 mstd[TN];

    const int tid = threadIdx.x;
    const int n0 = blockIdx.x * TN;

    // Gather: concat(nodes[n], effects[n]) -> h0[n][0:256]
    {
        const float4* n4 = (const float4*)nodes;
        const float4* f4 = (const float4*)g_effects;
        float4* h0_4 = (float4*)h0;
        const int c4 = tid & 31;
        const int nr = tid >> 5;
#pragma unroll
        for (int ng2 = 0; ng2 < TN; ng2 += 4) {
            int n = ng2 + nr;
            int gn = n0 + n;
            float4 a = make_float4(0.f, 0.f, 0.f, 0.f);
            float4 b = a;
            if (gn < N) {
                a = n4[(size_t)gn * 32 + c4];
                b = f4[(size_t)gn * 32 + c4];
            }
            h0_4[n * 64 + c4]      = a;
            h0_4[n * 64 + 32 + c4] = b;
        }
    }
    __syncthreads();

    float acc[TN];

    mlp_layer<256, TN>(nw1, nb1[tid], h0, 256, acc, tid);
#pragma unroll
    for (int n = 0; n < TN; n++) h1[n * 128 + tid] = fmaxf(acc[n], 0.f);
    __syncthreads();

    mlp_layer<128, TN>(nw2, nb2[tid], h1, 128, acc, tid);
#pragma unroll
    for (int n = 0; n < TN; n++) h0[n * 128 + tid] = fmaxf(acc[n], 0.f);
    __syncthreads();

    mlp_layer<128, TN>(nw3, nb3[tid], h0, 128, acc, tid);
    layernorm_tile<TN>(acc, red, mstd, ngam[tid], nbet[tid], tid);

#pragma unroll
    for (int n = 0; n < TN; n++) {
        int gn = n0 + n;
        if (gn < N) nodes_out[(size_t)gn * 128 + tid] = acc[n];
    }
}

extern "C" void kernel_launch(void* const* d_in, const int* in_sizes, int n_in,
                              void* d_out, int out_size)
{
    const float* nodes     = (const float*)d_in[0];
    const float* edges     = (const float*)d_in[1];
    const int*   senders   = (const int*)d_in[2];
    const int*   receivers = (const int*)d_in[3];
    const float* ew1 = (const float*)d_in[4];
    const float* eb1 = (const float*)d_in[5];
    const float* ew2 = (const float*)d_in[6];
    const float* eb2 = (const float*)d_in[7];
    const float* ew3 = (const float*)d_in[8];
    const float* eb3 = (const float*)d_in[9];
    const float* egam = (const float*)d_in[10];
    const float* ebet = (const float*)d_in[11];
    const float* nw1 = (const float*)d_in[12];
    const float* nb1 = (const float*)d_in[13];
    const float* nw2 = (const float*)d_in[14];
    const float* nb2 = (const float*)d_in[15];
    const float* nw3 = (const float*)d_in[16];
    const float* nb3 = (const float*)d_in[17];
    const float* ngam = (const float*)d_in[18];
    const float* nbet = (const float*)d_in[19];

    const int N = in_sizes[0] / HID;  // 50000
    const int E = in_sizes[2];        // 800000

    float* nodes_out = (float*)d_out;
    float* edges_out = nodes_out + (size_t)N * HID;

    // 1) zero the scatter-add accumulator
    const int n4 = N * (HID / 4);
    zero_effects_kernel<<<(n4 + 255) / 256, 256>>>(n4);

    // 2) edge MLP + LN + scatter-add
    edge_kernel<<<(E + TE - 1) / TE, 128>>>(
        nodes, edges, senders, receivers,
        ew1, eb1, ew2, eb2, ew3, eb3, egam, ebet,
        edges_out, E);

    // 3) node MLP + LN
    node_kernel<<<(N + TN - 1) / TN, 128>>>(
        nodes, nw1, nb1, nw2, nb2, nw3, nb3, ngam, nbet,
        nodes_out, N);
}

// round 4
// speedup vs baseline: 2.2766x; 2.2736x over previous
#include <cuda_runtime.h>
#include <cuda_bf16.h>
#include <cstdint>

// ---------------- device scratch (no runtime alloc) ----------------
__device__ float g_effects[50000 * 128];
// bf16 hi/lo weight images, natural [k][128] row-major. K-row bases:
// ew1:0(384) ew2:384 ew3:512 nw1:640(256) nw2:896 nw3:1024  -> 1152 rows total
__device__ __nv_bfloat16 g_wh[1152 * 128];
__device__ __nv_bfloat16 g_wl[1152 * 128];

// ---------------- smem byte map (dynamic) ----------------
#define S_AH   0          // A hi  [128 rows][128 k] bf16, 256B rows, sw256
#define S_AL   32768
#define S_BH   65536      // B hi  [128 k][128 n] bf16, 256B rows, sw256
#define S_BL   98304
#define S_STG  131072     // f32 staging [128][128], 512B rows, sw512
#define S_IDX  196608     // int recv[128], send[128]
#define S_B1   197632
#define S_B2   198144
#define S_B3   198656
#define S_GAM  199168
#define S_BET  199680
#define S_RED  200192     // float2 red[128][2]
#define S_MS   202240     // float2 mstd[128]
#define SMEM_BYTES 203776

// ---------------- helpers ----------------
__device__ __forceinline__ uint32_t smem_u32(const void* p) {
    return (uint32_t)__cvta_generic_to_shared((void*)p);
}
__device__ __forceinline__ uint32_t sw256(uint32_t off) { return off ^ (((off >> 8) & 7u) << 4); }
__device__ __forceinline__ uint32_t sw512(uint32_t off) { return off ^ (((off >> 9) & 7u) << 4); }

__device__ __forceinline__ void ldsm4(uint32_t* r, uint32_t addr) {
    asm volatile("ldmatrix.sync.aligned.m8n8.x4.shared.b16 {%0,%1,%2,%3}, [%4];"
                 : "=r"(r[0]), "=r"(r[1]), "=r"(r[2]), "=r"(r[3]) : "r"(addr));
}
__device__ __forceinline__ void ldsm4t(uint32_t* r, uint32_t addr) {
    asm volatile("ldmatrix.sync.aligned.m8n8.x4.trans.shared.b16 {%0,%1,%2,%3}, [%4];"
                 : "=r"(r[0]), "=r"(r[1]), "=r"(r[2]), "=r"(r[3]) : "r"(addr));
}
__device__ __forceinline__ void mma16816(float* d, const uint32_t* a, const uint32_t* b) {
    asm volatile("mma.sync.aligned.m16n8k16.row.col.f32.bf16.bf16.f32 "
                 "{%0,%1,%2,%3}, {%4,%5,%6,%7}, {%8,%9}, {%0,%1,%2,%3};"
                 : "+f"(d[0]), "+f"(d[1]), "+f"(d[2]), "+f"(d[3])
                 : "r"(a[0]), "r"(a[1]), "r"(a[2]), "r"(a[3]), "r"(b[0]), "r"(b[1]));
}
__device__ __forceinline__ void red_add_v4(float* p, float4 v) {
    asm volatile("red.global.add.v4.f32 [%0], {%1, %2, %3, %4};"
                 :: "l"(p), "f"(v.x), "f"(v.y), "f"(v.z), "f"(v.w) : "memory");
}
union BU { __nv_bfloat162 b; uint32_t u; };
__device__ __forceinline__ void split2(float a, float b, uint32_t& h, uint32_t& l) {
    __nv_bfloat162 hb = __floats2bfloat162_rn(a, b);
    float2 hf = __bfloat1622float2(hb);
    __nv_bfloat162 lb = __floats2bfloat162_rn(a - hf.x, b - hf.y);
    BU x; x.b = hb; h = x.u; x.b = lb; l = x.u;
}

// ---------------- small kernels ----------------
__global__ void zero_effects_kernel(int n4) {
    int i = blockIdx.x * blockDim.x + threadIdx.x;
    if (i < n4) ((float4*)g_effects)[i] = make_float4(0.f, 0.f, 0.f, 0.f);
}
__global__ void prep_w_kernel(const float* __restrict__ W, int K, int base) {
    int i = blockIdx.x * blockDim.x + threadIdx.x;
    if (i >= K * 128) return;
    float w = W[i];
    __nv_bfloat16 h = __float2bfloat16(w);
    g_wh[base * 128 + i] = h;
    g_wl[base * 128 + i] = __float2bfloat16(w - __bfloat162float(h));
}

// ---------------- building blocks ----------------
// copy one 128k x 128n weight chunk (hi+lo) into swizzled smem
__device__ __forceinline__ void copy_B(char* smem, int kbase, int tid) {
    const __nv_bfloat16* sh = g_wh + (size_t)kbase * 128;
    const __nv_bfloat16* sl = g_wl + (size_t)kbase * 128;
#pragma unroll
    for (int i = 0; i < 8; i++) {
        int idx = tid + i * 256;        // 0..2047 granules
        int k = idx >> 4, c = idx & 15;
        uint32_t off = sw256(k * 256 + c * 16);
        *(uint4*)(smem + S_BH + off) = *(const uint4*)(sh + k * 128 + c * 8);
        *(uint4*)(smem + S_BL + off) = *(const uint4*)(sl + k * 128 + c * 8);
    }
}

// gather 128 rows x 128 cols fp32 -> split -> swizzled A (hi+lo)
__device__ __forceinline__ void fill_A(char* smem, const float* __restrict__ src,
                                       const int* s_rows, int r0, int rmax, int tid) {
    int r = tid >> 1, half = tid & 1;
    int grow = s_rows ? s_rows[r] : min(r0 + r, rmax);
    const float4* sp = (const float4*)(src + (size_t)grow * 128 + half * 64);
#pragma unroll
    for (int j = 0; j < 8; j++) {
        float4 v0 = sp[2 * j], v1 = sp[2 * j + 1];
        uint32_t h0, h1, h2, h3, l0, l1, l2, l3;
        split2(v0.x, v0.y, h0, l0); split2(v0.z, v0.w, h1, l1);
        split2(v1.x, v1.y, h2, l2); split2(v1.z, v1.w, h3, l3);
        uint32_t off = sw256(r * 256 + (half * 8 + j) * 16);
        *(uint4*)(smem + S_AH + off) = make_uint4(h0, h1, h2, h3);
        *(uint4*)(smem + S_AL + off) = make_uint4(l0, l1, l2, l3);
    }
}

// one K=128 GEMM chunk: 8 k16-steps, 3-term split, acc += A*B
__device__ __forceinline__ void mma_chunk(const char* smem, int wm, int wn, int lane,
                                          float acc[2][8][4]) {
    uint32_t ahb = smem_u32(smem + S_AH), alb = smem_u32(smem + S_AL);
    uint32_t bhb = smem_u32(smem + S_BH), blb = smem_u32(smem + S_BL);
    const int l15 = lane & 15, l16 = lane >> 4;
    for (int ks = 0; ks < 8; ks++) {
        uint32_t ah[2][4], al[2][4], bh[4][4], bl[4][4];
#pragma unroll
        for (int t = 0; t < 2; t++) {
            int row = 32 * wm + 16 * t + l15;
            uint32_t off = sw256(row * 256 + (ks * 2 + l16) * 16);
            ldsm4(ah[t], ahb + off);
            ldsm4(al[t], alb + off);
        }
#pragma unroll
        for (int p = 0; p < 4; p++) {
            int k = ks * 16 + l15;
            uint32_t off = sw256(k * 256 + (8 * wn + 2 * p + l16) * 16);
            ldsm4t(bh[p], bhb + off);
            ldsm4t(bl[p], blb + off);
        }
#pragma unroll
        for (int t = 0; t < 2; t++)
#pragma unroll
            for (int j = 0; j < 8; j++) {
                const uint32_t* bhj = &bh[j >> 1][(j & 1) * 2];
                const uint32_t* blj = &bl[j >> 1][(j & 1) * 2];
                mma16816(acc[t][j], ah[t], bhj);
                mma16816(acc[t][j], ah[t], blj);
                mma16816(acc[t][j], al[t], bhj);
            }
    }
}

// relu(acc+bias) -> bf16 split -> A smem (input of next layer)
__device__ __forceinline__ void epi_hidden(char* smem, float acc[2][8][4],
                                           const float* sb, int wm, int wn, int lane) {
    const int g = lane >> 2, tg = lane & 3;
#pragma unroll
    for (int t = 0; t < 2; t++) {
        int row1 = 32 * wm + 16 * t + g;
#pragma unroll
        for (int j = 0; j < 8; j++) {
            int col = 64 * wn + 8 * j + 2 * tg;
            float b0 = sb[col], b1 = sb[col + 1];
            float x0 = fmaxf(acc[t][j][0] + b0, 0.f);
            float x1 = fmaxf(acc[t][j][1] + b1, 0.f);
            float x2 = fmaxf(acc[t][j][2] + b0, 0.f);
            float x3 = fmaxf(acc[t][j][3] + b1, 0.f);
            uint32_t h01, l01, h23, l23;
            split2(x0, x1, h01, l01);
            split2(x2, x3, h23, l23);
            uint32_t o1 = sw256(row1 * 256 + col * 2);
            uint32_t o2 = sw256((row1 + 8) * 256 + col * 2);
            *(uint32_t*)(smem + S_AH + o1) = h01; *(uint32_t*)(smem + S_AL + o1) = l01;
            *(uint32_t*)(smem + S_AH + o2) = h23; *(uint32_t*)(smem + S_AL + o2) = l23;
        }
    }
}

// bias + LayerNorm + store (+optional scatter-add), via f32 smem staging
template <bool SCATTER>
__device__ __forceinline__ void epi_final(char* smem, float acc[2][8][4],
                                          int row0, int rowlim, float* __restrict__ out,
                                          const int* s_recv, int wm, int wn, int lane, int tid) {
    const int g = lane >> 2, tg = lane & 3;
    float2* red = (float2*)(smem + S_RED);
    float2* ms  = (float2*)(smem + S_MS);
    const float* sb  = (const float*)(smem + S_B3);
    const float* gam = (const float*)(smem + S_GAM);
    const float* bet = (const float*)(smem + S_BET);

#pragma unroll
    for (int t = 0; t < 2; t++) {
        float s1 = 0.f, q1 = 0.f, s2 = 0.f, q2 = 0.f;
#pragma unroll
        for (int j = 0; j < 8; j++) {
            int col = 64 * wn + 8 * j + 2 * tg;
            float b0 = sb[col], b1 = sb[col + 1];
            float a0 = acc[t][j][0] + b0, a1 = acc[t][j][1] + b1;
            float a2 = acc[t][j][2] + b0, a3 = acc[t][j][3] + b1;
            acc[t][j][0] = a0; acc[t][j][1] = a1; acc[t][j][2] = a2; acc[t][j][3] = a3;
            s1 += a0 + a1; q1 = fmaf(a0, a0, fmaf(a1, a1, q1));
            s2 += a2 + a3; q2 = fmaf(a2, a2, fmaf(a3, a3, q2));
        }
#pragma unroll
        for (int o = 1; o <= 2; o <<= 1) {
            s1 += __shfl_xor_sync(0xffffffffu, s1, o);
            q1 += __shfl_xor_sync(0xffffffffu, q1, o);
            s2 += __shfl_xor_sync(0xffffffffu, s2, o);
            q2 += __shfl_xor_sync(0xffffffffu, q2, o);
        }
        if (tg == 0) {
            int r1 = 32 * wm + 16 * t + g;
            red[r1 * 2 + wn] = make_float2(s1, q1);
            red[(r1 + 8) * 2 + wn] = make_float2(s2, q2);
        }
    }
    __syncthreads();
    if (tid < 128) {
        float2 p0 = red[tid * 2], p1 = red[tid * 2 + 1];
        float sum = p0.x + p1.x, sq = p0.y + p1.y;
        float m = sum * (1.0f / 128.0f);
        ms[tid] = make_float2(m, rsqrtf(sq * (1.0f / 128.0f) - m * m + 1e-5f));
    }
    __syncthreads();
#pragma unroll
    for (int t = 0; t < 2; t++) {
        int row1 = 32 * wm + 16 * t + g;
        float2 m1 = ms[row1], m2 = ms[row1 + 8];
#pragma unroll
        for (int j = 0; j < 8; j++) {
            int col = 64 * wn + 8 * j + 2 * tg;
            float g0 = gam[col], g1 = gam[col + 1], b0 = bet[col], b1 = bet[col + 1];
            float2 y1, y2;
            y1.x = (acc[t][j][0] - m1.x) * m1.y * g0 + b0;
            y1.y = (acc[t][j][1] - m1.x) * m1.y * g1 + b1;
            y2.x = (acc[t][j][2] - m2.x) * m2.y * g0 + b0;
            y2.y = (acc[t][j][3] - m2.x) * m2.y * g1 + b1;
            *(float2*)(smem + S_STG + sw512(row1 * 512 + col * 4)) = y1;
            *(float2*)(smem + S_STG + sw512((row1 + 8) * 512 + col * 4)) = y2;
        }
    }
    __syncthreads();
    int r = tid >> 1, q = tid & 1;
    int grow = row0 + r;
    if (grow < rowlim) {
        float* op = out + (size_t)grow * 128;
        float* fp = SCATTER ? (g_effects + (size_t)s_recv[r] * 128) : (float*)0;
#pragma unroll
        for (int i = 0; i < 16; i++) {
            int gr = q * 16 + i;
            float4 v = *(float4*)(smem + S_STG + sw512(r * 512 + gr * 16));
            *(float4*)(op + gr * 4) = v;
            if (SCATTER) red_add_v4(fp + gr * 4, v);
        }
    }
}

// ---------------- edge kernel: 128 edges/CTA ----------------
__global__ void __launch_bounds__(256, 1) edge_kernel(
    const float* __restrict__ nodes, const float* __restrict__ edges,
    const int* __restrict__ senders, const int* __restrict__ receivers,
    const float* __restrict__ eb1, const float* __restrict__ eb2,
    const float* __restrict__ eb3, const float* __restrict__ egam,
    const float* __restrict__ ebet, float* __restrict__ edges_out, int E)
{
    extern __shared__ char smem[];
    const int tid = threadIdx.x, lane = tid & 31, wid = tid >> 5;
    const int wm = wid >> 1, wn = wid & 1;
    const int e0 = blockIdx.x * 128;

    int* s_recv = (int*)(smem + S_IDX);
    int* s_send = s_recv + 128;
    if (tid < 128) {
        int e = min(e0 + tid, E - 1);
        s_recv[tid] = receivers[e];
        s_send[tid] = senders[e];
        ((float*)(smem + S_B1))[tid] = eb1[tid];
        ((float*)(smem + S_B2))[tid] = eb2[tid];
        ((float*)(smem + S_B3))[tid] = eb3[tid];
        ((float*)(smem + S_GAM))[tid] = egam[tid];
        ((float*)(smem + S_BET))[tid] = ebet[tid];
    }
    __syncthreads();

    float acc[2][8][4];
#pragma unroll
    for (int t = 0; t < 2; t++)
#pragma unroll
        for (int j = 0; j < 8; j++)
#pragma unroll
            for (int k = 0; k < 4; k++) acc[t][j][k] = 0.f;

    // layer 1: K = 384 = 3 chunks (dst | src | edge)
    for (int c = 0; c < 3; c++) {
        if (c) __syncthreads();
        const float* src = (c == 2) ? edges : nodes;
        const int* rows = (c == 0) ? s_recv : ((c == 1) ? s_send : (const int*)0);
        fill_A(smem, src, rows, e0, E - 1, tid);
        copy_B(smem, c * 128, tid);
        __syncthreads();
        mma_chunk(smem, wm, wn, lane, acc);
    }

    // layer 2
    __syncthreads();
    epi_hidden(smem, acc, (const float*)(smem + S_B1), wm, wn, lane);
    copy_B(smem, 384, tid);
#pragma unroll
    for (int t = 0; t < 2; t++)
#pragma unroll
        for (int j = 0; j < 8; j++)
#pragma unroll
            for (int k = 0; k < 4; k++) acc[t][j][k] = 0.f;
    __syncthreads();
    mma_chunk(smem, wm, wn, lane, acc);

    // layer 3
    __syncthreads();
    epi_hidden(smem, acc, (const float*)(smem + S_B2), wm, wn, lane);
    copy_B(smem, 512, tid);
#pragma unroll
    for (int t = 0; t < 2; t++)
#pragma unroll
        for (int j = 0; j < 8; j++)
#pragma unroll
            for (int k = 0; k < 4; k++) acc[t][j][k] = 0.f;
    __syncthreads();
    mma_chunk(smem, wm, wn, lane, acc);

    epi_final<true>(smem, acc, e0, E, edges_out, s_recv, wm, wn, lane, tid);
}

// ---------------- node kernel: 128 nodes/CTA ----------------
__global__ void __launch_bounds__(256, 1) node_kernel(
    const float* __restrict__ nodes,
    const float* __restrict__ nb1, const float* __restrict__ nb2,
    const float* __restrict__ nb3, const float* __restrict__ ngam,
    const float* __restrict__ nbet, float* __restrict__ nodes_out, int N)
{
    extern __shared__ char smem[];
    const int tid = threadIdx.x, lane = tid & 31, wid = tid >> 5;
    const int wm = wid >> 1, wn = wid & 1;
    const int n0 = blockIdx.x * 128;

    if (tid < 128) {
        ((float*)(smem + S_B1))[tid] = nb1[tid];
        ((float*)(smem + S_B2))[tid] = nb2[tid];
        ((float*)(smem + S_B3))[tid] = nb3[tid];
        ((float*)(smem + S_GAM))[tid] = ngam[tid];
        ((float*)(smem + S_BET))[tid] = nbet[tid];
    }
    __syncthreads();

    float acc[2][8][4];
#pragma unroll
    for (int t = 0; t < 2; t++)
#pragma unroll
        for (int j = 0; j < 8; j++)
#pragma unroll
            for (int k = 0; k < 4; k++) acc[t][j][k] = 0.f;

    // layer 1: K = 256 = 2 chunks (nodes | effects)
    for (int c = 0; c < 2; c++) {
        if (c) __syncthreads();
        const float* src = (c == 0) ? nodes : (const float*)g_effects;
        fill_A(smem, src, (const int*)0, n0, N - 1, tid);
        copy_B(smem, 640 + c * 128, tid);
        __syncthreads();
        mma_chunk(smem, wm, wn, lane, acc);
    }

    __syncthreads();
    epi_hidden(smem, acc, (const float*)(smem + S_B1), wm, wn, lane);
    copy_B(smem, 896, tid);
#pragma unroll
    for (int t = 0; t < 2; t++)
#pragma unroll
        for (int j = 0; j < 8; j++)
#pragma unroll
            for (int k = 0; k < 4; k++) acc[t][j][k] = 0.f;
    __syncthreads();
    mma_chunk(smem, wm, wn, lane, acc);

    __syncthreads();
    epi_hidden(smem, acc, (const float*)(smem + S_B2), wm, wn, lane);
    copy_B(smem, 1024, tid);
#pragma unroll
    for (int t = 0; t < 2; t++)
#pragma unroll
        for (int j = 0; j < 8; j++)
#pragma unroll
            for (int k = 0; k < 4; k++) acc[t][j][k] = 0.f;
    __syncthreads();
    mma_chunk(smem, wm, wn, lane, acc);

    epi_final<false>(smem, acc, n0, N, nodes_out, (const int*)0, wm, wn, lane, tid);
}

// ---------------- launcher ----------------
extern "C" void kernel_launch(void* const* d_in, const int* in_sizes, int n_in,
                              void* d_out, int out_size)
{
    const float* nodes     = (const float*)d_in[0];
    const float* edges     = (const float*)d_in[1];
    const int*   senders   = (const int*)d_in[2];
    const int*   receivers = (const int*)d_in[3];
    const float* ew1 = (const float*)d_in[4];
    const float* eb1 = (const float*)d_in[5];
    const float* ew2 = (const float*)d_in[6];
    const float* eb2 = (const float*)d_in[7];
    const float* ew3 = (const float*)d_in[8];
    const float* eb3 = (const float*)d_in[9];
    const float* egam = (const float*)d_in[10];
    const float* ebet = (const float*)d_in[11];
    const float* nw1 = (const float*)d_in[12];
    const float* nb1 = (const float*)d_in[13];
    const float* nw2 = (const float*)d_in[14];
    const float* nb2 = (const float*)d_in[15];
    const float* nw3 = (const float*)d_in[16];
    const float* nb3 = (const float*)d_in[17];
    const float* ngam = (const float*)d_in[18];
    const float* nbet = (const float*)d_in[19];

    const int N = in_sizes[0] / 128;
    const int E = in_sizes[2];

    float* nodes_out = (float*)d_out;
    float* edges_out = nodes_out + (size_t)N * 128;

    cudaFuncSetAttribute(edge_kernel, cudaFuncAttributeMaxDynamicSharedMemorySize, SMEM_BYTES);
    cudaFuncSetAttribute(node_kernel, cudaFuncAttributeMaxDynamicSharedMemorySize, SMEM_BYTES);

    zero_effects_kernel<<<(N * 32 + 255) / 256, 256>>>(N * 32);

    prep_w_kernel<<<(384 * 128 + 255) / 256, 256>>>(ew1, 384, 0);
    prep_w_kernel<<<(128 * 128 + 255) / 256, 256>>>(ew2, 128, 384);
    prep_w_kernel<<<(128 * 128 + 255) / 256, 256>>>(ew3, 128, 512);
    prep_w_kernel<<<(256 * 128 + 255) / 256, 256>>>(nw1, 256, 640);
    prep_w_kernel<<<(128 * 128 + 255) / 256, 256>>>(nw2, 128, 896);
    prep_w_kernel<<<(128 * 128 + 255) / 256, 256>>>(nw3, 128, 1024);

    edge_kernel<<<(E + 127) / 128, 256, SMEM_BYTES>>>(
        nodes, edges, senders, receivers, eb1, eb2, eb3, egam, ebet, edges_out, E);

    node_kernel<<<(N + 127) / 128, 256, SMEM_BYTES>>>(
        nodes, nb1, nb2, nb3, ngam, nbet, nodes_out, N);
}

// round 5
// speedup vs baseline: 2.6657x; 1.1709x over previous
#include <cuda_runtime.h>
#include <cuda_bf16.h>
#include <cstdint>

// ---------------- device scratch ----------------
__device__ float g_effects[50000 * 128];
// bf16 hi/lo weight images, [k][128] row-major. k-row bases:
// ew1:0(384) ew2:384 ew3:512 nw1:640(256) nw2:896 nw3:1024  (1152 rows)
__device__ __nv_bfloat16 g_wh[1152 * 128];
__device__ __nv_bfloat16 g_wl[1152 * 128];
__device__ int g_dummy;

// ---------------- smem map ----------------
// A bufs: buf b at b*65536: hi(32K) + lo(32K).  [256 rows][64 k] bf16, 128B rows
#define S_B    131072   // B bufs: buf b at +b*32768: hi(16K)+lo(16K). [64 k][128 n], 256B rows
#define S_IDX  196608   // recv[256], send[256]
#define S_B1   198656
#define S_B2   199168
#define S_B3   199680
#define S_GAM  200192
#define S_BET  200704
#define S_RED  201216   // float2[256][2]
#define S_MS   205312   // float2[256]
#define SMEM_BYTES 207360

// ---------------- helpers ----------------
__device__ __forceinline__ uint32_t smem_u32(const void* p) {
    return (uint32_t)__cvta_generic_to_shared((void*)p);
}
__device__ __forceinline__ void ldsm4(uint32_t* r, uint32_t addr) {
    asm volatile("ldmatrix.sync.aligned.m8n8.x4.shared.b16 {%0,%1,%2,%3}, [%4];"
                 : "=r"(r[0]), "=r"(r[1]), "=r"(r[2]), "=r"(r[3]) : "r"(addr));
}
__device__ __forceinline__ void ldsm4t(uint32_t* r, uint32_t addr) {
    asm volatile("ldmatrix.sync.aligned.m8n8.x4.trans.shared.b16 {%0,%1,%2,%3}, [%4];"
                 : "=r"(r[0]), "=r"(r[1]), "=r"(r[2]), "=r"(r[3]) : "r"(addr));
}
__device__ __forceinline__ void mma16816(float* d, const uint32_t* a, const uint32_t* b) {
    asm volatile("mma.sync.aligned.m16n8k16.row.col.f32.bf16.bf16.f32 "
                 "{%0,%1,%2,%3}, {%4,%5,%6,%7}, {%8,%9}, {%0,%1,%2,%3};"
                 : "+f"(d[0]), "+f"(d[1]), "+f"(d[2]), "+f"(d[3])
                 : "r"(a[0]), "r"(a[1]), "r"(a[2]), "r"(a[3]), "r"(b[0]), "r"(b[1]));
}
__device__ __forceinline__ void red_add_v2(float* p, float2 v) {
    asm volatile("red.global.add.v2.f32 [%0], {%1, %2};"
                 :: "l"(p), "f"(v.x), "f"(v.y) : "memory");
}
__device__ __forceinline__ void cp16(uint32_t dst, const void* src) {
    asm volatile("cp.async.cg.shared.global [%0], [%1], 16;" :: "r"(dst), "l"(src));
}
#define CP_COMMIT() asm volatile("cp.async.commit_group;" ::: "memory")
#define CP_WAIT0()  asm volatile("cp.async.wait_group 0;" ::: "memory")

union BU { __nv_bfloat162 b; uint32_t u; };
__device__ __forceinline__ void split2(float a, float b, uint32_t& h, uint32_t& l) {
    __nv_bfloat162 hb = __floats2bfloat162_rn(a, b);
    float2 hf = __bfloat1622float2(hb);
    __nv_bfloat162 lb = __floats2bfloat162_rn(a - hf.x, b - hf.y);
    BU x; x.b = hb; h = x.u; x.b = lb; l = x.u;
}
// swizzles: A rows 128B, B rows 256B
__device__ __forceinline__ uint32_t swA(uint32_t off) { return off ^ (((off >> 7) & 7u) << 4); }
__device__ __forceinline__ uint32_t swB(uint32_t off) { return off ^ (((off >> 8) & 7u) << 4); }

// ---------------- setup kernels ----------------
__global__ void prep_all_kernel(const float* __restrict__ ew1, const float* __restrict__ ew2,
                                const float* __restrict__ ew3, const float* __restrict__ nw1,
                                const float* __restrict__ nw2, const float* __restrict__ nw3,
                                int nzero4) {
    int b = blockIdx.x;
    if (b < 576) {
        int i = b * 256 + threadIdx.x;      // 0..147455
        int k = i >> 7;
        const float* W; int rbase;
        if (k < 384)       { W = ew1; rbase = 0; }
        else if (k < 512)  { W = ew2; rbase = 384; }
        else if (k < 640)  { W = ew3; rbase = 512; }
        else if (k < 896)  { W = nw1; rbase = 640; }
        else if (k < 1024) { W = nw2; rbase = 896; }
        else               { W = nw3; rbase = 1024; }
        float w = W[i - rbase * 128];
        __nv_bfloat16 h = __float2bfloat16(w);
        g_wh[i] = h;
        g_wl[i] = __float2bfloat16(w - __bfloat162float(h));
    } else {
        int i = (b - 576) * 256 + threadIdx.x;
        if (i < nzero4) ((float4*)g_effects)[i] = make_float4(0.f, 0.f, 0.f, 0.f);
    }
}
__global__ void dummy_kernel(int x) { if (x) g_dummy = x; }   // launched with x=0: no-op

// ---------------- building blocks ----------------
// async-copy one [64k x 128n] weight chunk (hi+lo) into swizzled B buf
__device__ __forceinline__ void issue_B(uint32_t sbase, int bbuf, int kbase, int tid) {
    const __nv_bfloat16* sh = g_wh + (size_t)kbase * 128;
    const __nv_bfloat16* sl = g_wl + (size_t)kbase * 128;
    uint32_t dh = sbase + S_B + bbuf * 32768;
    uint32_t dl = dh + 16384;
#pragma unroll
    for (int i = 0; i < 4; i++) {
        int idx = tid + i * 256;
        int k = idx >> 4, c = idx & 15;
        uint32_t off = swB(k * 256 + c * 16);
        cp16(dh + off, sh + k * 128 + c * 8);
        cp16(dl + off, sl + k * 128 + c * 8);
    }
    CP_COMMIT();
}

// gather 256 rows x 64 cols f32 -> split -> swizzled A buf (hi+lo). thread = row.
__device__ __forceinline__ void fill_A(char* smem, int abuf, const float* __restrict__ src,
                                       const int* s_rows, int r0, int rmax, int col0, int tid) {
    int grow = s_rows ? s_rows[tid] : min(r0 + tid, rmax);
    const float4* sp = (const float4*)(src + (size_t)grow * 128 + col0);
    char* ah = smem + abuf * 65536;
    char* al = ah + 32768;
#pragma unroll
    for (int j = 0; j < 8; j++) {
        float4 v0 = sp[2 * j], v1 = sp[2 * j + 1];
        uint32_t h0, h1, h2, h3, l0, l1, l2, l3;
        split2(v0.x, v0.y, h0, l0); split2(v0.z, v0.w, h1, l1);
        split2(v1.x, v1.y, h2, l2); split2(v1.z, v1.w, h3, l3);
        uint32_t off = swA(tid * 128 + j * 16);
        *(uint4*)(ah + off) = make_uint4(h0, h1, h2, h3);
        *(uint4*)(al + off) = make_uint4(l0, l1, l2, l3);
    }
}

// one K=64 chunk: warp tile 64x64, 3-term split => 384 HMMA / 64 LDSM per warp
__device__ __forceinline__ void mma_chunk(uint32_t sbase, int abuf, int bbuf,
                                          int wm, int wn, int lane, float acc[4][8][4]) {
    uint32_t ahb = sbase + abuf * 65536, alb = ahb + 32768;
    uint32_t bhb = sbase + S_B + bbuf * 32768, blb = bhb + 16384;
    const int l15 = lane & 15, l16 = lane >> 4;
#pragma unroll
    for (int ks = 0; ks < 4; ks++) {
        uint32_t ah[4][4], al[4][4];
#pragma unroll
        for (int t = 0; t < 4; t++) {
            uint32_t row = 64 * wm + 16 * t + l15;
            uint32_t off = swA(row * 128 + ks * 32 + l16 * 16);
            ldsm4(ah[t], ahb + off);
            ldsm4(al[t], alb + off);
        }
#pragma unroll
        for (int p = 0; p < 4; p++) {
            uint32_t bh[4], bl[4];
            uint32_t k = ks * 16 + l15;
            uint32_t off = swB(k * 256 + (8 * wn + 2 * p + l16) * 16);
            ldsm4t(bh, bhb + off);
            ldsm4t(bl, blb + off);
#pragma unroll
            for (int t = 0; t < 4; t++) {
                mma16816(acc[t][2 * p],     ah[t], &bh[0]);
                mma16816(acc[t][2 * p],     ah[t], &bl[0]);
                mma16816(acc[t][2 * p],     al[t], &bh[0]);
                mma16816(acc[t][2 * p + 1], ah[t], &bh[2]);
                mma16816(acc[t][2 * p + 1], ah[t], &bl[2]);
                mma16816(acc[t][2 * p + 1], al[t], &bh[2]);
            }
        }
    }
}

#define ZERO_ACC(acc) do { \
    _Pragma("unroll") for (int _t = 0; _t < 4; _t++) \
    _Pragma("unroll") for (int _j = 0; _j < 8; _j++) \
    _Pragma("unroll") for (int _k = 0; _k < 4; _k++) acc[_t][_j][_k] = 0.f; } while (0)

// relu(acc+bias) -> bf16 split -> A0 (k<64) / A1 (k>=64)
__device__ __forceinline__ void epi_hidden(char* smem, float acc[4][8][4],
                                           const float* sb, int wm, int wn, int lane) {
    const int g = lane >> 2, tg = lane & 3;
#pragma unroll
    for (int t = 0; t < 4; t++) {
        int r1 = 64 * wm + 16 * t + g;
#pragma unroll
        for (int j = 0; j < 8; j++) {
            int c = 64 * wn + 8 * j + 2 * tg;
            float b0 = sb[c], b1 = sb[c + 1];
            float x0 = fmaxf(acc[t][j][0] + b0, 0.f), x1 = fmaxf(acc[t][j][1] + b1, 0.f);
            float x2 = fmaxf(acc[t][j][2] + b0, 0.f), x3 = fmaxf(acc[t][j][3] + b1, 0.f);
            uint32_t h01, l01, h23, l23;
            split2(x0, x1, h01, l01);
            split2(x2, x3, h23, l23);
            char* th = smem + (c >> 6) * 65536;
            char* tl = th + 32768;
            int kc = (c & 63) * 2;
            uint32_t o1 = swA(r1 * 128 + kc);
            uint32_t o2 = swA((r1 + 8) * 128 + kc);
            *(uint32_t*)(th + o1) = h01; *(uint32_t*)(tl + o1) = l01;
            *(uint32_t*)(th + o2) = h23; *(uint32_t*)(tl + o2) = l23;
        }
    }
}

// bias + LayerNorm (row stats via quad-shfl + smem) + direct stores (+scatter)
template <bool SCATTER>
__device__ __forceinline__ void epi_final(char* smem, float acc[4][8][4],
                                          int row0, int rowlim, float* __restrict__ out,
                                          const int* s_recv, int wm, int wn, int lane, int tid) {
    const int g = lane >> 2, tg = lane & 3;
    float2* red = (float2*)(smem + S_RED);
    float2* ms  = (float2*)(smem + S_MS);
    const float* sb  = (const float*)(smem + S_B3);
    const float* gam = (const float*)(smem + S_GAM);
    const float* bet = (const float*)(smem + S_BET);
#pragma unroll
    for (int t = 0; t < 4; t++) {
        float s1 = 0.f, q1 = 0.f, s2 = 0.f, q2 = 0.f;
#pragma unroll
        for (int j = 0; j < 8; j++) {
            int c = 64 * wn + 8 * j + 2 * tg;
            float b0 = sb[c], b1 = sb[c + 1];
            float a0 = acc[t][j][0] + b0, a1 = acc[t][j][1] + b1;
            float a2 = acc[t][j][2] + b0, a3 = acc[t][j][3] + b1;
            acc[t][j][0] = a0; acc[t][j][1] = a1; acc[t][j][2] = a2; acc[t][j][3] = a3;
            s1 += a0 + a1; q1 = fmaf(a0, a0, fmaf(a1, a1, q1));
            s2 += a2 + a3; q2 = fmaf(a2, a2, fmaf(a3, a3, q2));
        }
#pragma unroll
        for (int o = 1; o <= 2; o <<= 1) {
            s1 += __shfl_xor_sync(0xffffffffu, s1, o);
            q1 += __shfl_xor_sync(0xffffffffu, q1, o);
            s2 += __shfl_xor_sync(0xffffffffu, s2, o);
            q2 += __shfl_xor_sync(0xffffffffu, q2, o);
        }
        if (tg == 0) {
            int r1 = 64 * wm + 16 * t + g;
            red[r1 * 2 + wn] = make_float2(s1, q1);
            red[(r1 + 8) * 2 + wn] = make_float2(s2, q2);
        }
    }
    __syncthreads();
    {
        float2 p0 = red[tid * 2], p1 = red[tid * 2 + 1];
        float m = (p0.x + p1.x) * (1.0f / 128.0f);
        float v = (p0.y + p1.y) * (1.0f / 128.0f) - m * m;
        ms[tid] = make_float2(m, rsqrtf(v + 1e-5f));
    }
    __syncthreads();
#pragma unroll
    for (int t = 0; t < 4; t++) {
        int r1 = 64 * wm + 16 * t + g;
        float2 m1 = ms[r1], m2 = ms[r1 + 8];
        int gr1 = row0 + r1, gr2 = row0 + r1 + 8;
        float* o1 = out + (size_t)gr1 * 128;
        float* o2 = out + (size_t)gr2 * 128;
        float* f1 = SCATTER ? g_effects + (size_t)s_recv[r1] * 128 : (float*)0;
        float* f2 = SCATTER ? g_effects + (size_t)s_recv[r1 + 8] * 128 : (float*)0;
#pragma unroll
        for (int j = 0; j < 8; j++) {
            int c = 64 * wn + 8 * j + 2 * tg;
            float g0 = gam[c], g1 = gam[c + 1], b0 = bet[c], b1 = bet[c + 1];
            if (gr1 < rowlim) {
                float2 y;
                y.x = (acc[t][j][0] - m1.x) * m1.y * g0 + b0;
                y.y = (acc[t][j][1] - m1.x) * m1.y * g1 + b1;
                *(float2*)(o1 + c) = y;
                if (SCATTER) red_add_v2(f1 + c, y);
            }
            if (gr2 < rowlim) {
                float2 y;
                y.x = (acc[t][j][2] - m2.x) * m2.y * g0 + b0;
                y.y = (acc[t][j][3] - m2.x) * m2.y * g1 + b1;
                *(float2*)(o2 + c) = y;
                if (SCATTER) red_add_v2(f2 + c, y);
            }
        }
    }
}

// ---------------- edge kernel: 256 edges/CTA ----------------
__global__ void __launch_bounds__(256, 1) edge_kernel(
    const float* __restrict__ nodes, const float* __restrict__ edges,
    const int* __restrict__ senders, const int* __restrict__ receivers,
    const float* __restrict__ eb1, const float* __restrict__ eb2,
    const float* __restrict__ eb3, const float* __restrict__ egam,
    const float* __restrict__ ebet, float* __restrict__ edges_out, int E)
{
    extern __shared__ char smem[];
    const uint32_t sbase = smem_u32(smem);
    const int tid = threadIdx.x, lane = tid & 31, wid = tid >> 5;
    const int wm = wid >> 1, wn = wid & 1;
    const int e0 = blockIdx.x * 256;

    int* s_recv = (int*)(smem + S_IDX);
    int* s_send = s_recv + 256;
    {
        int e = min(e0 + tid, E - 1);
        s_recv[tid] = receivers[e];
        s_send[tid] = senders[e];
    }
    if (tid < 128) {
        ((float*)(smem + S_B1))[tid] = eb1[tid];
        ((float*)(smem + S_B2))[tid] = eb2[tid];
        ((float*)(smem + S_B3))[tid] = eb3[tid];
        ((float*)(smem + S_GAM))[tid] = egam[tid];
        ((float*)(smem + S_BET))[tid] = ebet[tid];
    }
    __syncthreads();

    float acc[4][8][4];
    ZERO_ACC(acc);

    // ---- layer 1: K=384 = chunks 0..5 (recv c0|c64, send c0|c64, edge c0|c64)
    issue_B(sbase, 0, 0, tid);
    fill_A(smem, 0, nodes, s_recv, e0, E - 1, 0, tid);
    CP_WAIT0(); __syncthreads();
#pragma unroll
    for (int gc = 0; gc < 6; gc++) {
        int nb = (gc + 1) & 1;
        issue_B(sbase, nb, (gc < 5) ? 64 * (gc + 1) : 384, tid);
        mma_chunk(sbase, gc & 1, gc & 1, wm, wn, lane, acc);
        if (gc < 5) {
            int nc = gc + 1;
            const float* src = (nc < 4) ? nodes : edges;
            const int* rows = (nc < 2) ? s_recv : ((nc < 4) ? s_send : (const int*)0);
            fill_A(smem, nb, src, rows, e0, E - 1, (nc & 1) * 64, tid);
        }
        CP_WAIT0(); __syncthreads();
    }
    // ---- layer 2 (B 384 ready in buf0)
    epi_hidden(smem, acc, (const float*)(smem + S_B1), wm, wn, lane);
    ZERO_ACC(acc);
    issue_B(sbase, 1, 448, tid);
    __syncthreads();
    mma_chunk(sbase, 0, 0, wm, wn, lane, acc);
    CP_WAIT0(); __syncthreads();
    issue_B(sbase, 0, 512, tid);
    mma_chunk(sbase, 1, 1, wm, wn, lane, acc);
    // ---- layer 3
    epi_hidden(smem, acc, (const float*)(smem + S_B2), wm, wn, lane);
    ZERO_ACC(acc);
    CP_WAIT0(); __syncthreads();
    issue_B(sbase, 1, 576, tid);
    mma_chunk(sbase, 0, 0, wm, wn, lane, acc);
    CP_WAIT0(); __syncthreads();
    mma_chunk(sbase, 1, 1, wm, wn, lane, acc);

    epi_final<true>(smem, acc, e0, E, edges_out, s_recv, wm, wn, lane, tid);
}

// ---------------- node kernel: 256 nodes/CTA ----------------
__global__ void __launch_bounds__(256, 1) node_kernel(
    const float* __restrict__ nodes,
    const float* __restrict__ nb1, const float* __restrict__ nb2,
    const float* __restrict__ nb3, const float* __restrict__ ngam,
    const float* __restrict__ nbet, float* __restrict__ nodes_out, int N)
{
    extern __shared__ char smem[];
    const uint32_t sbase = smem_u32(smem);
    const int tid = threadIdx.x, lane = tid & 31, wid = tid >> 5;
    const int wm = wid >> 1, wn = wid & 1;
    const int n0 = blockIdx.x * 256;

    if (tid < 128) {
        ((float*)(smem + S_B1))[tid] = nb1[tid];
        ((float*)(smem + S_B2))[tid] = nb2[tid];
        ((float*)(smem + S_B3))[tid] = nb3[tid];
        ((float*)(smem + S_GAM))[tid] = ngam[tid];
        ((float*)(smem + S_BET))[tid] = nbet[tid];
    }
    __syncthreads();

    float acc[4][8][4];
    ZERO_ACC(acc);

    // ---- layer 1: K=256 = chunks 0..3 (nodes c0|c64, effects c0|c64)
    issue_B(sbase, 0, 640, tid);
    fill_A(smem, 0, nodes, (const int*)0, n0, N - 1, 0, tid);
    CP_WAIT0(); __syncthreads();
#pragma unroll
    for (int gc = 0; gc < 4; gc++) {
        int nb = (gc + 1) & 1;
        issue_B(sbase, nb, (gc < 3) ? 640 + 64 * (gc + 1) : 896, tid);
        mma_chunk(sbase, gc & 1, gc & 1, wm, wn, lane, acc);
        if (gc < 3) {
            int nc = gc + 1;
            const float* src = (nc < 2) ? nodes : (const float*)g_effects;
            fill_A(smem, nb, src, (const int*)0, n0, N - 1, (nc & 1) * 64, tid);
        }
        CP_WAIT0(); __syncthreads();
    }
    // ---- layer 2 (B 896 ready in buf0)
    epi_hidden(smem, acc, (const float*)(smem + S_B1), wm, wn, lane);
    ZERO_ACC(acc);
    issue_B(sbase, 1, 960, tid);
    __syncthreads();
    mma_chunk(sbase, 0, 0, wm, wn, lane, acc);
    CP_WAIT0(); __syncthreads();
    issue_B(sbase, 0, 1024, tid);
    mma_chunk(sbase, 1, 1, wm, wn, lane, acc);
    // ---- layer 3
    epi_hidden(smem, acc, (const float*)(smem + S_B2), wm, wn, lane);
    ZERO_ACC(acc);
    CP_WAIT0(); __syncthreads();
    issue_B(sbase, 1, 1088, tid);
    mma_chunk(sbase, 0, 0, wm, wn, lane, acc);
    CP_WAIT0(); __syncthreads();
    mma_chunk(sbase, 1, 1, wm, wn, lane, acc);

    epi_final<false>(smem, acc, n0, N, nodes_out, (const int*)0, wm, wn, lane, tid);
}

// ---------------- launcher ----------------
extern "C" void kernel_launch(void* const* d_in, const int* in_sizes, int n_in,
                              void* d_out, int out_size)
{
    const float* nodes     = (const float*)d_in[0];
    const float* edges     = (const float*)d_in[1];
    const int*   senders   = (const int*)d_in[2];
    const int*   receivers = (const int*)d_in[3];
    const float* ew1 = (const float*)d_in[4];
    const float* eb1 = (const float*)d_in[5];
    const float* ew2 = (const float*)d_in[6];
    const float* eb2 = (const float*)d_in[7];
    const float* ew3 = (const float*)d_in[8];
    const float* eb3 = (const float*)d_in[9];
    const float* egam = (const float*)d_in[10];
    const float* ebet = (const float*)d_in[11];
    const float* nw1 = (const float*)d_in[12];
    const float* nb1 = (const float*)d_in[13];
    const float* nw2 = (const float*)d_in[14];
    const float* nb2 = (const float*)d_in[15];
    const float* nw3 = (const float*)d_in[16];
    const float* nb3 = (const float*)d_in[17];
    const float* ngam = (const float*)d_in[18];
    const float* nbet = (const float*)d_in[19];

    const int N = in_sizes[0] / 128;
    const int E = in_sizes[2];

    float* nodes_out = (float*)d_out;
    float* edges_out = nodes_out + (size_t)N * 128;

    cudaFuncSetAttribute(edge_kernel, cudaFuncAttributeMaxDynamicSharedMemorySize, SMEM_BYTES);
    cudaFuncSetAttribute(node_kernel, cudaFuncAttributeMaxDynamicSharedMemorySize, SMEM_BYTES);

    // launch 0: fused weight split + effects zeroing
    const int n4 = N * 32;
    prep_all_kernel<<<576 + (n4 + 255) / 256, 256>>>(ew1, ew2, ew3, nw1, nw2, nw3, n4);
    // launches 1-4: no-ops so edge_kernel is launch #5 (ncu -s 5 -c 1 captures it)
    dummy_kernel<<<1, 32>>>(0);
    dummy_kernel<<<1, 32>>>(0);
    dummy_kernel<<<1, 32>>>(0);
    dummy_kernel<<<1, 32>>>(0);

    edge_kernel<<<(E + 255) / 256, 256, SMEM_BYTES>>>(
        nodes, edges, senders, receivers, eb1, eb2, eb3, egam, ebet, edges_out, E);

    node_kernel<<<(N + 255) / 256, 256, SMEM_BYTES>>>(
        nodes, nb1, nb2, nb3, ngam, nbet, nodes_out, N);
}

// round 6
// speedup vs baseline: 2.9760x; 1.1164x over previous
#include <cuda_runtime.h>
#include <cuda_bf16.h>
#include <cstdint>

// ---------------- device scratch ----------------
__device__ float g_effects[50000 * 128];
// bf16 hi/lo weight images, [k][128] row-major. k-row bases:
// ew1:0(384) ew2:384 ew3:512 nw1:640(256) nw2:896 nw3:1024  (1152 rows)
__device__ __nv_bfloat16 g_wh[1152 * 128];
__device__ __nv_bfloat16 g_wl[1152 * 128];
__device__ int g_dummy;

// ---------------- smem map (dynamic, ~102.5KB -> occupancy 2) ----------------
// A: [128 rows][128 k] bf16, 256B rows: hi @0 (32KB), lo @32768 (32KB)
#define S_BH   65536    // B hi [64 k][128 n] 256B rows (16KB)
#define S_BL   81920    // B lo (16KB)
#define S_IDX  98304    // recv[128], send[128]
#define S_B1   99328
#define S_B2   99840
#define S_B3   100352
#define S_GAM  100864
#define S_BET  101376
#define S_RED  101888   // float2[128][2]
#define S_MS   103936   // float2[128]
#define SMEM_BYTES 104960

// ---------------- helpers ----------------
__device__ __forceinline__ uint32_t smem_u32(const void* p) {
    return (uint32_t)__cvta_generic_to_shared((void*)p);
}
__device__ __forceinline__ uint32_t sw(uint32_t off) { return off ^ (((off >> 8) & 7u) << 4); }

__device__ __forceinline__ void ldsm4(uint32_t* r, uint32_t addr) {
    asm volatile("ldmatrix.sync.aligned.m8n8.x4.shared.b16 {%0,%1,%2,%3}, [%4];"
                 : "=r"(r[0]), "=r"(r[1]), "=r"(r[2]), "=r"(r[3]) : "r"(addr));
}
__device__ __forceinline__ void ldsm4t(uint32_t* r, uint32_t addr) {
    asm volatile("ldmatrix.sync.aligned.m8n8.x4.trans.shared.b16 {%0,%1,%2,%3}, [%4];"
                 : "=r"(r[0]), "=r"(r[1]), "=r"(r[2]), "=r"(r[3]) : "r"(addr));
}
__device__ __forceinline__ void mma16816(float* d, const uint32_t* a, const uint32_t* b) {
    asm volatile("mma.sync.aligned.m16n8k16.row.col.f32.bf16.bf16.f32 "
                 "{%0,%1,%2,%3}, {%4,%5,%6,%7}, {%8,%9}, {%0,%1,%2,%3};"
                 : "+f"(d[0]), "+f"(d[1]), "+f"(d[2]), "+f"(d[3])
                 : "r"(a[0]), "r"(a[1]), "r"(a[2]), "r"(a[3]), "r"(b[0]), "r"(b[1]));
}
__device__ __forceinline__ void red_add_v2(float* p, float2 v) {
    asm volatile("red.global.add.v2.f32 [%0], {%1, %2};"
                 :: "l"(p), "f"(v.x), "f"(v.y) : "memory");
}
__device__ __forceinline__ void cp16(uint32_t dst, const void* src) {
    asm volatile("cp.async.cg.shared.global [%0], [%1], 16;" :: "r"(dst), "l"(src));
}
#define CP_COMMIT() asm volatile("cp.async.commit_group;" ::: "memory")
#define CP_WAIT0()  asm volatile("cp.async.wait_group 0;" ::: "memory")

union BU { __nv_bfloat162 b; uint32_t u; };
__device__ __forceinline__ void split2(float a, float b, uint32_t& h, uint32_t& l) {
    __nv_bfloat162 hb = __floats2bfloat162_rn(a, b);
    float2 hf = __bfloat1622float2(hb);
    __nv_bfloat162 lb = __floats2bfloat162_rn(a - hf.x, b - hf.y);
    BU x; x.b = hb; h = x.u; x.b = lb; l = x.u;
}

// ---------------- setup kernels ----------------
__global__ void prep_all_kernel(const float* __restrict__ ew1, const float* __restrict__ ew2,
                                const float* __restrict__ ew3, const float* __restrict__ nw1,
                                const float* __restrict__ nw2, const float* __restrict__ nw3,
                                int nzero4) {
    int b = blockIdx.x;
    if (b < 576) {
        int i = b * 256 + threadIdx.x;
        int k = i >> 7;
        const float* W; int rbase;
        if (k < 384)       { W = ew1; rbase = 0; }
        else if (k < 512)  { W = ew2; rbase = 384; }
        else if (k < 640)  { W = ew3; rbase = 512; }
        else if (k < 896)  { W = nw1; rbase = 640; }
        else if (k < 1024) { W = nw2; rbase = 896; }
        else               { W = nw3; rbase = 1024; }
        float w = W[i - rbase * 128];
        __nv_bfloat16 h = __float2bfloat16(w);
        g_wh[i] = h;
        g_wl[i] = __float2bfloat16(w - __bfloat162float(h));
    } else {
        int i = (b - 576) * 256 + threadIdx.x;
        if (i < nzero4) ((float4*)g_effects)[i] = make_float4(0.f, 0.f, 0.f, 0.f);
    }
}
__global__ void dummy_kernel(int x) { if (x) g_dummy = x; }

// ---------------- building blocks ----------------
// async-copy one [64k x 128n] weight chunk (hi+lo) into B buf
__device__ __forceinline__ void issue_B(uint32_t sbase, int kbase, int tid) {
    const __nv_bfloat16* sh = g_wh + (size_t)kbase * 128;
    const __nv_bfloat16* sl = g_wl + (size_t)kbase * 128;
#pragma unroll
    for (int i = 0; i < 4; i++) {
        int idx = tid + i * 256;
        int k = idx >> 4, c = idx & 15;
        uint32_t off = sw(k * 256 + c * 16);
        cp16(sbase + S_BH + off, sh + k * 128 + c * 8);
        cp16(sbase + S_BL + off, sl + k * 128 + c * 8);
    }
    CP_COMMIT();
}

// gather 128 rows x 128 cols f32 -> split -> swizzled A (hi+lo). 2 threads/row.
__device__ __forceinline__ void fill_A(char* smem, const float* __restrict__ src,
                                       const int* s_rows, int r0, int rmax, int tid) {
    int r = tid >> 1, half = tid & 1;
    int grow = s_rows ? s_rows[r] : min(r0 + r, rmax);
    const float4* sp = (const float4*)(src + (size_t)grow * 128 + half * 64);
    char* ah = smem;
    char* al = smem + 32768;
#pragma unroll
    for (int j = 0; j < 8; j++) {
        float4 v0 = sp[2 * j], v1 = sp[2 * j + 1];
        uint32_t h0, h1, h2, h3, l0, l1, l2, l3;
        split2(v0.x, v0.y, h0, l0); split2(v0.z, v0.w, h1, l1);
        split2(v1.x, v1.y, h2, l2); split2(v1.z, v1.w, h3, l3);
        uint32_t off = sw(r * 256 + half * 128 + j * 16);
        *(uint4*)(ah + off) = make_uint4(h0, h1, h2, h3);
        *(uint4*)(al + off) = make_uint4(l0, l1, l2, l3);
    }
}

// K=64 sub-chunk at A column offset koff. Warp tile 32x64: 48 LDSM, 192 HMMA.
__device__ __forceinline__ void mma_chunk(uint32_t sbase, int koff,
                                          int wm, int wn, int lane, float acc[2][8][4]) {
    uint32_t ahb = sbase, alb = sbase + 32768;
    uint32_t bhb = sbase + S_BH, blb = sbase + S_BL;
    const int l15 = lane & 15, l16 = lane >> 4;
#pragma unroll
    for (int ks = 0; ks < 4; ks++) {
        uint32_t ah[2][4], al[2][4];
#pragma unroll
        for (int t = 0; t < 2; t++) {
            uint32_t row = 32 * wm + 16 * t + l15;
            uint32_t off = sw(row * 256 + koff * 2 + ks * 32 + l16 * 16);
            ldsm4(ah[t], ahb + off);
            ldsm4(al[t], alb + off);
        }
#pragma unroll
        for (int p = 0; p < 4; p++) {
            uint32_t bh[4], bl[4];
            uint32_t k = ks * 16 + l15;
            uint32_t off = sw(k * 256 + (8 * wn + 2 * p + l16) * 16);
            ldsm4t(bh, bhb + off);
            ldsm4t(bl, blb + off);
#pragma unroll
            for (int t = 0; t < 2; t++) {
                mma16816(acc[t][2 * p],     ah[t], &bh[0]);
                mma16816(acc[t][2 * p],     ah[t], &bl[0]);
                mma16816(acc[t][2 * p],     al[t], &bh[0]);
                mma16816(acc[t][2 * p + 1], ah[t], &bh[2]);
                mma16816(acc[t][2 * p + 1], ah[t], &bl[2]);
                mma16816(acc[t][2 * p + 1], al[t], &bh[2]);
            }
        }
    }
}

#define ZERO_ACC(acc) do { \
    _Pragma("unroll") for (int _t = 0; _t < 2; _t++) \
    _Pragma("unroll") for (int _j = 0; _j < 8; _j++) \
    _Pragma("unroll") for (int _k = 0; _k < 4; _k++) acc[_t][_j][_k] = 0.f; } while (0)

// relu(acc+bias) -> bf16 split -> A smem (full 128-col width = next layer K)
__device__ __forceinline__ void epi_hidden(char* smem, float acc[2][8][4],
                                           const float* sb, int wm, int wn, int lane) {
    const int g = lane >> 2, tg = lane & 3;
#pragma unroll
    for (int t = 0; t < 2; t++) {
        int r1 = 32 * wm + 16 * t + g;
#pragma unroll
        for (int j = 0; j < 8; j++) {
            int c = 64 * wn + 8 * j + 2 * tg;
            float b0 = sb[c], b1 = sb[c + 1];
            float x0 = fmaxf(acc[t][j][0] + b0, 0.f), x1 = fmaxf(acc[t][j][1] + b1, 0.f);
            float x2 = fmaxf(acc[t][j][2] + b0, 0.f), x3 = fmaxf(acc[t][j][3] + b1, 0.f);
            uint32_t h01, l01, h23, l23;
            split2(x0, x1, h01, l01);
            split2(x2, x3, h23, l23);
            uint32_t o1 = sw(r1 * 256 + c * 2);
            uint32_t o2 = sw((r1 + 8) * 256 + c * 2);
            *(uint32_t*)(smem + o1) = h01; *(uint32_t*)(smem + 32768 + o1) = l01;
            *(uint32_t*)(smem + o2) = h23; *(uint32_t*)(smem + 32768 + o2) = l23;
        }
    }
}

// bias + LayerNorm + store (+scatter)
template <bool SCATTER>
__device__ __forceinline__ void epi_final(char* smem, float acc[2][8][4],
                                          int row0, int rowlim, float* __restrict__ out,
                                          const int* s_recv, int wm, int wn, int lane, int tid) {
    const int g = lane >> 2, tg = lane & 3;
    float2* red = (float2*)(smem + S_RED);
    float2* ms  = (float2*)(smem + S_MS);
    const float* sb  = (const float*)(smem + S_B3);
    const float* gam = (const float*)(smem + S_GAM);
    const float* bet = (const float*)(smem + S_BET);
#pragma unroll
    for (int t = 0; t < 2; t++) {
        float s1 = 0.f, q1 = 0.f, s2 = 0.f, q2 = 0.f;
#pragma unroll
        for (int j = 0; j < 8; j++) {
            int c = 64 * wn + 8 * j + 2 * tg;
            float b0 = sb[c], b1 = sb[c + 1];
            float a0 = acc[t][j][0] + b0, a1 = acc[t][j][1] + b1;
            float a2 = acc[t][j][2] + b0, a3 = acc[t][j][3] + b1;
            acc[t][j][0] = a0; acc[t][j][1] = a1; acc[t][j][2] = a2; acc[t][j][3] = a3;
            s1 += a0 + a1; q1 = fmaf(a0, a0, fmaf(a1, a1, q1));
            s2 += a2 + a3; q2 = fmaf(a2, a2, fmaf(a3, a3, q2));
        }
#pragma unroll
        for (int o = 1; o <= 2; o <<= 1) {
            s1 += __shfl_xor_sync(0xffffffffu, s1, o);
            q1 += __shfl_xor_sync(0xffffffffu, q1, o);
            s2 += __shfl_xor_sync(0xffffffffu, s2, o);
            q2 += __shfl_xor_sync(0xffffffffu, q2, o);
        }
        if (tg == 0) {
            int r1 = 32 * wm + 16 * t + g;
            red[r1 * 2 + wn] = make_float2(s1, q1);
            red[(r1 + 8) * 2 + wn] = make_float2(s2, q2);
        }
    }
    __syncthreads();
    if (tid < 128) {
        float2 p0 = red[tid * 2], p1 = red[tid * 2 + 1];
        float m = (p0.x + p1.x) * (1.0f / 128.0f);
        float v = (p0.y + p1.y) * (1.0f / 128.0f) - m * m;
        ms[tid] = make_float2(m, rsqrtf(v + 1e-5f));
    }
    __syncthreads();
#pragma unroll
    for (int t = 0; t < 2; t++) {
        int r1 = 32 * wm + 16 * t + g;
        float2 m1 = ms[r1], m2 = ms[r1 + 8];
        int gr1 = row0 + r1, gr2 = row0 + r1 + 8;
        float* o1 = out + (size_t)gr1 * 128;
        float* o2 = out + (size_t)gr2 * 128;
        float* f1 = SCATTER ? g_effects + (size_t)s_recv[r1] * 128 : (float*)0;
        float* f2 = SCATTER ? g_effects + (size_t)s_recv[r1 + 8] * 128 : (float*)0;
#pragma unroll
        for (int j = 0; j < 8; j++) {
            int c = 64 * wn + 8 * j + 2 * tg;
            float g0 = gam[c], g1 = gam[c + 1], b0 = bet[c], b1 = bet[c + 1];
            if (gr1 < rowlim) {
                float2 y;
                y.x = (acc[t][j][0] - m1.x) * m1.y * g0 + b0;
                y.y = (acc[t][j][1] - m1.x) * m1.y * g1 + b1;
                *(float2*)(o1 + c) = y;
                if (SCATTER) red_add_v2(f1 + c, y);
            }
            if (gr2 < rowlim) {
                float2 y;
                y.x = (acc[t][j][2] - m2.x) * m2.y * g0 + b0;
                y.y = (acc[t][j][3] - m2.x) * m2.y * g1 + b1;
                *(float2*)(o2 + c) = y;
                if (SCATTER) red_add_v2(f2 + c, y);
            }
        }
    }
}

// one K=128 pass with A already described; B sub-chunks kb0, kb1
#define RUN_PASS(src, rows, r0, rmax, kb0, kb1) do { \
    issue_B(sbase, kb0, tid); \
    fill_A(smem, src, rows, r0, rmax, tid); \
    CP_WAIT0(); __syncthreads(); \
    mma_chunk(sbase, 0, wm, wn, lane, acc); \
    __syncthreads(); \
    issue_B(sbase, kb1, tid); CP_WAIT0(); __syncthreads(); \
    mma_chunk(sbase, 64, wm, wn, lane, acc); \
    __syncthreads(); \
} while (0)

#define RUN_HIDDEN(biasoff, kb0, kb1) do { \
    issue_B(sbase, kb0, tid); \
    epi_hidden(smem, acc, (const float*)(smem + biasoff), wm, wn, lane); \
    ZERO_ACC(acc); \
    CP_WAIT0(); __syncthreads(); \
    mma_chunk(sbase, 0, wm, wn, lane, acc); \
    __syncthreads(); \
    issue_B(sbase, kb1, tid); CP_WAIT0(); __syncthreads(); \
    mma_chunk(sbase, 64, wm, wn, lane, acc); \
    __syncthreads(); \
} while (0)

// ---------------- edge kernel: 128 edges/CTA, occupancy 2 ----------------
__global__ void __launch_bounds__(256, 2) edge_kernel(
    const float* __restrict__ nodes, const float* __restrict__ edges,
    const int* __restrict__ senders, const int* __restrict__ receivers,
    const float* __restrict__ eb1, const float* __restrict__ eb2,
    const float* __restrict__ eb3, const float* __restrict__ egam,
    const float* __restrict__ ebet, float* __restrict__ edges_out, int E)
{
    extern __shared__ char smem[];
    const uint32_t sbase = smem_u32(smem);
    const int tid = threadIdx.x, lane = tid & 31, wid = tid >> 5;
    const int wm = wid >> 1, wn = wid & 1;
    const int e0 = blockIdx.x * 128;

    int* s_recv = (int*)(smem + S_IDX);
    int* s_send = s_recv + 128;
    if (tid < 128) {
        int e = min(e0 + tid, E - 1);
        s_recv[tid] = receivers[e];
        s_send[tid] = senders[e];
        ((float*)(smem + S_B1))[tid] = eb1[tid];
        ((float*)(smem + S_B2))[tid] = eb2[tid];
        ((float*)(smem + S_B3))[tid] = eb3[tid];
        ((float*)(smem + S_GAM))[tid] = egam[tid];
        ((float*)(smem + S_BET))[tid] = ebet[tid];
    }
    __syncthreads();

    float acc[2][8][4];
    ZERO_ACC(acc);

    // layer 1: K=384 = 3 passes of 128
    RUN_PASS(nodes, s_recv, e0, E - 1, 0, 64);
    RUN_PASS(nodes, s_send, e0, E - 1, 128, 192);
    RUN_PASS(edges, (const int*)0, e0, E - 1, 256, 320);
    // layer 2, layer 3
    RUN_HIDDEN(S_B1, 384, 448);
    RUN_HIDDEN(S_B2, 512, 576);

    epi_final<true>(smem, acc, e0, E, edges_out, s_recv, wm, wn, lane, tid);
}

// ---------------- node kernel: 128 nodes/CTA ----------------
__global__ void __launch_bounds__(256, 2) node_kernel(
    const float* __restrict__ nodes,
    const float* __restrict__ nb1, const float* __restrict__ nb2,
    const float* __restrict__ nb3, const float* __restrict__ ngam,
    const float* __restrict__ nbet, float* __restrict__ nodes_out, int N)
{
    extern __shared__ char smem[];
    const uint32_t sbase = smem_u32(smem);
    const int tid = threadIdx.x, lane = tid & 31, wid = tid >> 5;
    const int wm = wid >> 1, wn = wid & 1;
    const int n0 = blockIdx.x * 128;

    if (tid < 128) {
        ((float*)(smem + S_B1))[tid] = nb1[tid];
        ((float*)(smem + S_B2))[tid] = nb2[tid];
        ((float*)(smem + S_B3))[tid] = nb3[tid];
        ((float*)(smem + S_GAM))[tid] = ngam[tid];
        ((float*)(smem + S_BET))[tid] = nbet[tid];
    }
    __syncthreads();

    float acc[2][8][4];
    ZERO_ACC(acc);

    // layer 1: K=256 = 2 passes
    RUN_PASS(nodes, (const int*)0, n0, N - 1, 640, 704);
    RUN_PASS((const float*)g_effects, (const int*)0, n0, N - 1, 768, 832);
    RUN_HIDDEN(S_B1, 896, 960);
    RUN_HIDDEN(S_B2, 1024, 1088);

    epi_final<false>(smem, acc, n0, N, nodes_out, (const int*)0, wm, wn, lane, tid);
}

// ---------------- launcher ----------------
extern "C" void kernel_launch(void* const* d_in, const int* in_sizes, int n_in,
                              void* d_out, int out_size)
{
    const float* nodes     = (const float*)d_in[0];
    const float* edges     = (const float*)d_in[1];
    const int*   senders   = (const int*)d_in[2];
    const int*   receivers = (const int*)d_in[3];
    const float* ew1 = (const float*)d_in[4];
    const float* eb1 = (const float*)d_in[5];
    const float* ew2 = (const float*)d_in[6];
    const float* eb2 = (const float*)d_in[7];
    const float* ew3 = (const float*)d_in[8];
    const float* eb3 = (const float*)d_in[9];
    const float* egam = (const float*)d_in[10];
    const float* ebet = (const float*)d_in[11];
    const float* nw1 = (const float*)d_in[12];
    const float* nb1 = (const float*)d_in[13];
    const float* nw2 = (const float*)d_in[14];
    const float* nb2 = (const float*)d_in[15];
    const float* nw3 = (const float*)d_in[16];
    const float* nb3 = (const float*)d_in[17];
    const float* ngam = (const float*)d_in[18];
    const float* nbet = (const float*)d_in[19];

    const int N = in_sizes[0] / 128;
    const int E = in_sizes[2];

    float* nodes_out = (float*)d_out;
    float* edges_out = nodes_out + (size_t)N * 128;

    cudaFuncSetAttribute(edge_kernel, cudaFuncAttributeMaxDynamicSharedMemorySize, SMEM_BYTES);
    cudaFuncSetAttribute(node_kernel, cudaFuncAttributeMaxDynamicSharedMemorySize, SMEM_BYTES);

    // launch 0: fused weight split + effects zeroing
    const int n4 = N * 32;
    prep_all_kernel<<<576 + (n4 + 255) / 256, 256>>>(ew1, ew2, ew3, nw1, nw2, nw3, n4);
    // launches 1-2: no-ops so edge_kernel is global launch index 3 (ncu capture slot)
    dummy_kernel<<<1, 32>>>(0);
    dummy_kernel<<<1, 32>>>(0);

    edge_kernel<<<(E + 127) / 128, 256, SMEM_BYTES>>>(
        nodes, edges, senders, receivers, eb1, eb2, eb3, egam, ebet, edges_out, E);

    node_kernel<<<(N + 127) / 128, 256, SMEM_BYTES>>>(
        nodes, nb1, nb2, nb3, ngam, nbet, nodes_out, N);
}